// round 13
// baseline (speedup 1.0000x reference)
#include <cuda_runtime.h>
#include <cuda_fp16.h>
#include <cstdint>

// ---------------- problem dims ----------------
#define MROWS 32768           // 4*8192 activation rows
#define KDIM  512
#define NDIM  512

// ---------------- GEMM tiling -----------------
#define BM 128
#define BN 128
#define BK 64
#define STAGES 3
#define STAGE_OP_BYTES (128 * 128)            // one operand, one stage: 128 rows x 128 B
#define STAGE_BYTES (2 * STAGE_OP_BYTES)      // A + B
#define SMEM_DYN (STAGES * STAGE_BYTES)       // 98304 B -> 2 CTAs/SM

#define NT_N (NDIM / BN)                      // 4
#define NTILES ((MROWS / BM) * NT_N)          // 1024
#define GRID 296                              // 2 CTAs/SM, fully resident

// ---------------- scratch ---------------------
// Plain fp16 casts. Error model (calibrated R7/R9/R12): ref's own gmac rounding
// ~2.0e-4 rel; fp16(w) cast 2.8e-4; fp16(x) cast 2.8e-4 -> ~4.55e-4 combined
// (R12 measured 4.552e-4), deterministic, 2x margin under the 1e-3 gate.
__device__ __half  g_A2[(size_t)MROWS * KDIM]; // 32 MB  fp16(x)
__device__ __half  g_B2[(size_t)NDIM * KDIM];  // 512 KB fp16(w)

// ---------------- helpers ---------------------
__device__ __forceinline__ uint32_t smem_u32(const void* p) {
    return (uint32_t)__cvta_generic_to_shared(p);
}

// ---------------- prep: pure fp16 cast --------
// Blocks [0,2048): x -> A2.  Blocks [2048,2112): w -> B2.
__global__ void k_cast_xw(const float* __restrict__ x, const float* __restrict__ w) {
    __half2* A2 = (__half2*)g_A2;
    __half2* B2 = (__half2*)g_B2;
    if (blockIdx.x < 2048) {
        size_t n4 = (size_t)MROWS * KDIM / 4;
        size_t stride = (size_t)2048 * blockDim.x;
        for (size_t i = (size_t)blockIdx.x * blockDim.x + threadIdx.x; i < n4; i += stride) {
            float4 v = ((const float4*)x)[i];
            A2[i * 2]     = __floats2half2_rn(v.x, v.y);
            A2[i * 2 + 1] = __floats2half2_rn(v.z, v.w);
        }
    } else {
        size_t n4 = (size_t)NDIM * KDIM / 4;
        size_t stride = (size_t)64 * blockDim.x;
        for (size_t i = (size_t)(blockIdx.x - 2048) * blockDim.x + threadIdx.x; i < n4; i += stride) {
            float4 v = ((const float4*)w)[i];
            B2[i * 2]     = __floats2half2_rn(v.x, v.y);
            B2[i * 2 + 1] = __floats2half2_rn(v.z, v.w);
        }
    }
}

// ---------------- persistent HMMA GEMM --------
// out[m][n] = sum_k A2[m,k]*B2[n,k];  128x128 tiles, BK=64, 3-stage cp.async
// pipeline that runs CONTINUOUSLY across tiles (global chunk counter g; the
// only full drain is on the final chunk). Tile t: bn = t&3, bm = t>>2, so the
// 4 CTAs running consecutive t share the A tile via L2. 2 CTAs/SM, grid=296.
extern __shared__ __half dynsmem[];

// Chunk g of this CTA: tile t = t0 + (g>>3)*GRID, k-slice kt = g&7,
// stage s = g%3. XOR-swizzled smem (chunk c of row r at c ^ (r&7)).
__device__ __forceinline__ void load_chunk(uint32_t sb, int g, int t0) {
    const int t = t0 + (g >> 3) * GRID;
    const int kt = g & 7;
    const size_t a_base = (size_t)(t >> 2) * BM * KDIM;
    const size_t b_base = (size_t)(t & 3) * BN * KDIM;
    const uint32_t As = sb + (uint32_t)(g % 3) * STAGE_BYTES;
    const uint32_t Bs = As + STAGE_OP_BYTES;
    const int k0 = kt * BK;
    const int tid = threadIdx.x;
    #pragma unroll
    for (int i = 0; i < 8; ++i) {
        int id = tid + i * 256;              // 0..2047 chunks of 16B
        bool isA = id < 1024;
        int loc = isA ? id : id - 1024;
        int row = loc >> 3, cc = loc & 7;
        const __half* src = isA
            ? &g_A2[a_base + (size_t)row * KDIM + k0 + cc * 8]
            : &g_B2[b_base + (size_t)row * KDIM + k0 + cc * 8];
        uint32_t phys = (uint32_t)(cc ^ (row & 7));
        uint32_t dst = (isA ? As : Bs) + (uint32_t)row * 128u + phys * 16u;
        asm volatile("cp.async.cg.shared.global [%0], [%1], 16;\n" :: "r"(dst), "l"(src));
    }
}

__global__ void __launch_bounds__(256, 2) k_gemm6(float* __restrict__ out) {
    const int t0 = blockIdx.x;
    const int tid = threadIdx.x;
    const int wid = tid >> 5, lane = tid & 31;
    const int warp_m = wid & 1;          // 0..1 -> 64 rows each
    const int warp_n = wid >> 1;         // 0..3 -> 32 cols each

    const uint32_t sb = smem_u32(dynsmem);
    const int ntiles = ((NTILES - 1 - t0) / GRID) + 1;   // t0 < 296 <= NTILES
    const int G = ntiles * 8;

    float acc[4][4][4];
    #pragma unroll
    for (int i = 0; i < 4; i++)
        #pragma unroll
        for (int j = 0; j < 4; j++)
            #pragma unroll
            for (int k = 0; k < 4; k++) acc[i][j][k] = 0.f;

    load_chunk(sb, 0, t0);
    asm volatile("cp.async.commit_group;\n");
    load_chunk(sb, 1, t0);
    asm volatile("cp.async.commit_group;\n");

    for (int g = 0; g < G; ++g) {
        if (g == G - 1) { asm volatile("cp.async.wait_group 0;\n"); }
        else            { asm volatile("cp.async.wait_group 1;\n"); }
        __syncthreads();
        // Stage (g+2)%3 was consumed at iteration g-1; refill after barrier.
        if (g + 2 < G) {
            load_chunk(sb, g + 2, t0);
            asm volatile("cp.async.commit_group;\n");
        }

        const uint32_t As = sb + (uint32_t)(g % 3) * STAGE_BYTES;
        const uint32_t Bs = As + STAGE_OP_BYTES;

        #pragma unroll
        for (int ks = 0; ks < BK / 16; ++ks) {
            uint32_t a[4][4];
            #pragma unroll
            for (int mf = 0; mf < 4; ++mf) {
                int row = warp_m * 64 + mf * 16 + (lane & 15);
                int chunk = ks * 2 + ((lane & 16) ? 1 : 0);
                uint32_t addr = As + (uint32_t)row * 128u
                              + (uint32_t)(chunk ^ (row & 7)) * 16u;
                asm volatile("ldmatrix.sync.aligned.m8n8.x4.shared.b16 {%0,%1,%2,%3}, [%4];"
                             : "=r"(a[mf][0]), "=r"(a[mf][1]), "=r"(a[mf][2]), "=r"(a[mf][3])
                             : "r"(addr));
            }
            uint32_t b[4][2];
            #pragma unroll
            for (int gg = 0; gg < 2; ++gg) {
                int nrow = warp_n * 32 + gg * 16 + ((lane >> 4) << 3) + (lane & 7);
                int chunk = ks * 2 + ((lane & 8) ? 1 : 0);
                uint32_t addr = Bs + (uint32_t)nrow * 128u
                              + (uint32_t)(chunk ^ (nrow & 7)) * 16u;
                asm volatile("ldmatrix.sync.aligned.m8n8.x4.shared.b16 {%0,%1,%2,%3}, [%4];"
                             : "=r"(b[gg * 2][0]), "=r"(b[gg * 2][1]),
                               "=r"(b[gg * 2 + 1][0]), "=r"(b[gg * 2 + 1][1])
                             : "r"(addr));
            }
            #pragma unroll
            for (int mf = 0; mf < 4; ++mf)
                #pragma unroll
                for (int nf = 0; nf < 4; ++nf) {
                    asm volatile(
                        "mma.sync.aligned.m16n8k16.row.col.f32.f16.f16.f32 "
                        "{%0,%1,%2,%3}, {%4,%5,%6,%7}, {%8,%9}, {%0,%1,%2,%3};"
                        : "+f"(acc[mf][nf][0]), "+f"(acc[mf][nf][1]),
                          "+f"(acc[mf][nf][2]), "+f"(acc[mf][nf][3])
                        : "r"(a[mf][0]), "r"(a[mf][1]), "r"(a[mf][2]), "r"(a[mf][3]),
                          "r"(b[nf][0]), "r"(b[nf][1]));
                }
        }

        if ((g & 7) == 7) {
            // Tile finished: register-only epilogue (next-tile loads stay in
            // flight beneath it), then reset accumulators.
            const int t = t0 + (g >> 3) * GRID;
            const size_t obase = (size_t)(t >> 2) * BM * NDIM + (size_t)(t & 3) * BN;
            #pragma unroll
            for (int mf = 0; mf < 4; ++mf)
                #pragma unroll
                for (int nf = 0; nf < 4; ++nf) {
                    int r0 = warp_m * 64 + mf * 16 + (lane >> 2);
                    int c0 = warp_n * 32 + nf * 8 + 2 * (lane & 3);
                    float* op = &out[obase + (size_t)r0 * NDIM + c0];
                    op[0] = acc[mf][nf][0];
                    op[1] = acc[mf][nf][1];
                    float* op2 = op + 8 * NDIM;
                    op2[0] = acc[mf][nf][2];
                    op2[1] = acc[mf][nf][3];
                    acc[mf][nf][0] = 0.f; acc[mf][nf][1] = 0.f;
                    acc[mf][nf][2] = 0.f; acc[mf][nf][3] = 0.f;
                }
        }
    }
}

// ---------------- launch ----------------------
extern "C" void kernel_launch(void* const* d_in, const int* in_sizes, int n_in,
                              void* d_out, int out_size) {
    const float* x = (const float*)d_in[0];
    const float* w = (const float*)d_in[1];
    if (n_in >= 2 && in_sizes[0] == NDIM * KDIM && in_sizes[1] == MROWS * KDIM) {
        const float* t = x; x = w; w = t;
    }

    cudaFuncSetAttribute(k_gemm6, cudaFuncAttributeMaxDynamicSharedMemorySize, SMEM_DYN);

    k_cast_xw<<<2112, 256>>>(x, w);                       // launch 1
    k_gemm6<<<GRID, 256, SMEM_DYN>>>((float*)d_out);      // launch 2 (ncu slot)
}

// round 15
// speedup vs baseline: 1.0711x; 1.0711x over previous
#include <cuda_runtime.h>
#include <cuda_fp16.h>
#include <cstdint>

// ---------------- problem dims ----------------
#define MROWS 32768           // 4*8192 activation rows
#define KDIM  512
#define NDIM  512

// ---------------- GEMM tiling -----------------
#define BM 128
#define BN 128
#define BK 64
#define STAGES 3
#define STAGE_OP_BYTES (128 * 128)            // one operand, one stage: 128 rows x 128 B
#define STAGE_BYTES (2 * STAGE_OP_BYTES)      // A + B
#define SMEM_DYN (STAGES * STAGE_BYTES)       // 98304 B -> 2 CTAs/SM

// ---------------- scratch ---------------------
// Plain fp16 casts. Error model (calibrated R7/R9/R12): ref's own gmac rounding
// ~2.0e-4 rel; fp16(w) cast 2.8e-4; fp16(x) cast 2.8e-4 -> 4.552e-4 combined
// (R12 measured), deterministic, 2x margin under the 1e-3 gate.
__device__ __half  g_A2[(size_t)MROWS * KDIM]; // 32 MB  fp16(x)
__device__ __half  g_B2[(size_t)NDIM * KDIM];  // 512 KB fp16(w)

// ---------------- helpers ---------------------
__device__ __forceinline__ uint32_t smem_u32(const void* p) {
    return (uint32_t)__cvta_generic_to_shared(p);
}

__device__ __forceinline__ uint4 pack8(const float4 v0, const float4 v1) {
    union { uint4 u; __half2 h[4]; } o;
    o.h[0] = __floats2half2_rn(v0.x, v0.y);
    o.h[1] = __floats2half2_rn(v0.z, v0.w);
    o.h[2] = __floats2half2_rn(v1.x, v1.y);
    o.h[3] = __floats2half2_rn(v1.z, v1.w);
    return o.u;
}

// ---------------- prep: pure fp16 cast --------
// Blocks [0,2048): x -> A2.  Blocks [2048,2112): w -> B2.
// 16B stores (STG.128 of 8 halves) and 4 independent 16B loads in flight
// per iteration (MLP=4 hides DRAM latency per the B300 model).
__global__ void k_cast_xw(const float* __restrict__ x, const float* __restrict__ w) {
    if (blockIdx.x < 2048) {
        const float4* x4 = (const float4*)x;
        uint4* A16 = (uint4*)g_A2;
        size_t n8 = (size_t)MROWS * KDIM / 8;            // 2M chunks of 8 floats
        size_t stride = (size_t)2048 * blockDim.x;       // 524288
        size_t i = (size_t)blockIdx.x * blockDim.x + threadIdx.x;
        for (; i + stride < n8; i += 2 * stride) {
            float4 a0 = x4[i * 2],            a1 = x4[i * 2 + 1];
            float4 b0 = x4[(i + stride) * 2], b1 = x4[(i + stride) * 2 + 1];
            A16[i]          = pack8(a0, a1);
            A16[i + stride] = pack8(b0, b1);
        }
        if (i < n8) {
            float4 a0 = x4[i * 2], a1 = x4[i * 2 + 1];
            A16[i] = pack8(a0, a1);
        }
    } else {
        const float4* w4 = (const float4*)w;
        uint4* B16 = (uint4*)g_B2;
        size_t n8 = (size_t)NDIM * KDIM / 8;             // 32768 chunks
        size_t stride = (size_t)64 * blockDim.x;         // 16384
        size_t i = (size_t)(blockIdx.x - 2048) * blockDim.x + threadIdx.x;
        for (; i < n8; i += stride) {
            float4 a0 = w4[i * 2], a1 = w4[i * 2 + 1];
            B16[i] = pack8(a0, a1);
        }
    }
}

// ---------------- HMMA GEMM (R12-proven) ------
// out[m][n] = sum_k A2[m,k]*B2[n,k];  128x128 tile, BK=64, K=512 (8 kt),
// 3 stages (wait_group 1), XOR-swizzled smem, 2 CTAs/SM.
extern __shared__ __half dynsmem[];

// Swizzled store layout per operand-stage: 128 rows x 8 chunks of 16B;
// chunk c of row r lives at physical chunk c ^ (r & 7).
__device__ __forceinline__ void gemm_load_stage(uint32_t smem_base_u32, int s, int kt,
                                                size_t a_base, size_t b_base) {
    const int tid = threadIdx.x;
    const uint32_t As = smem_base_u32 + (uint32_t)s * STAGE_BYTES;
    const uint32_t Bs = As + STAGE_OP_BYTES;
    const int k0 = kt * BK;
    #pragma unroll
    for (int i = 0; i < 8; ++i) {
        int id = tid + i * 256;              // 0..2047 chunks of 16B
        bool isA = id < 1024;
        int loc = isA ? id : id - 1024;
        int row = loc >> 3, cc = loc & 7;
        const __half* src = isA
            ? &g_A2[a_base + (size_t)row * KDIM + k0 + cc * 8]
            : &g_B2[b_base + (size_t)row * KDIM + k0 + cc * 8];
        uint32_t phys = (uint32_t)(cc ^ (row & 7));
        uint32_t dst = (isA ? As : Bs) + (uint32_t)row * 128u + phys * 16u;
        asm volatile("cp.async.cg.shared.global [%0], [%1], 16;\n" :: "r"(dst), "l"(src));
    }
}

__global__ void __launch_bounds__(256, 2) k_gemm5(float* __restrict__ out) {
    const int bn = blockIdx.x, bm = blockIdx.y;
    const int tid = threadIdx.x;
    const int wid = tid >> 5, lane = tid & 31;
    const int warp_m = wid & 1;          // 0..1 -> 64 rows each
    const int warp_n = wid >> 1;         // 0..3 -> 32 cols each

    const uint32_t sb = smem_u32(dynsmem);
    const size_t a_base = (size_t)bm * BM * KDIM;
    const size_t b_base = (size_t)bn * BN * KDIM;

    float acc[4][4][4];
    #pragma unroll
    for (int i = 0; i < 4; i++)
        #pragma unroll
        for (int j = 0; j < 4; j++)
            #pragma unroll
            for (int k = 0; k < 4; k++) acc[i][j][k] = 0.f;

    gemm_load_stage(sb, 0, 0, a_base, b_base);
    asm volatile("cp.async.commit_group;\n");
    gemm_load_stage(sb, 1, 1, a_base, b_base);
    asm volatile("cp.async.commit_group;\n");

    const int KT = KDIM / BK;   // 8
    for (int kt = 0; kt < KT; ++kt) {
        if (kt == KT - 1) { asm volatile("cp.async.wait_group 0;\n"); }
        else              { asm volatile("cp.async.wait_group 1;\n"); }
        __syncthreads();
        // Stage (kt+2)%3 was consumed in iteration kt-1; refill after barrier.
        if (kt + 2 < KT) {
            gemm_load_stage(sb, (kt + 2) % STAGES, kt + 2, a_base, b_base);
            asm volatile("cp.async.commit_group;\n");
        }

        const uint32_t As = sb + (uint32_t)(kt % STAGES) * STAGE_BYTES;
        const uint32_t Bs = As + STAGE_OP_BYTES;

        #pragma unroll
        for (int ks = 0; ks < BK / 16; ++ks) {
            uint32_t a[4][4];
            #pragma unroll
            for (int mf = 0; mf < 4; ++mf) {
                int row = warp_m * 64 + mf * 16 + (lane & 15);
                int chunk = ks * 2 + ((lane & 16) ? 1 : 0);
                uint32_t addr = As + (uint32_t)row * 128u
                              + (uint32_t)(chunk ^ (row & 7)) * 16u;
                asm volatile("ldmatrix.sync.aligned.m8n8.x4.shared.b16 {%0,%1,%2,%3}, [%4];"
                             : "=r"(a[mf][0]), "=r"(a[mf][1]), "=r"(a[mf][2]), "=r"(a[mf][3])
                             : "r"(addr));
            }
            uint32_t b[4][2];
            #pragma unroll
            for (int g = 0; g < 2; ++g) {
                int nrow = warp_n * 32 + g * 16 + ((lane >> 4) << 3) + (lane & 7);
                int chunk = ks * 2 + ((lane & 8) ? 1 : 0);
                uint32_t addr = Bs + (uint32_t)nrow * 128u
                              + (uint32_t)(chunk ^ (nrow & 7)) * 16u;
                asm volatile("ldmatrix.sync.aligned.m8n8.x4.shared.b16 {%0,%1,%2,%3}, [%4];"
                             : "=r"(b[g * 2][0]), "=r"(b[g * 2][1]),
                               "=r"(b[g * 2 + 1][0]), "=r"(b[g * 2 + 1][1])
                             : "r"(addr));
            }
            #pragma unroll
            for (int mf = 0; mf < 4; ++mf)
                #pragma unroll
                for (int nf = 0; nf < 4; ++nf) {
                    asm volatile(
                        "mma.sync.aligned.m16n8k16.row.col.f32.f16.f16.f32 "
                        "{%0,%1,%2,%3}, {%4,%5,%6,%7}, {%8,%9}, {%0,%1,%2,%3};"
                        : "+f"(acc[mf][nf][0]), "+f"(acc[mf][nf][1]),
                          "+f"(acc[mf][nf][2]), "+f"(acc[mf][nf][3])
                        : "r"(a[mf][0]), "r"(a[mf][1]), "r"(a[mf][2]), "r"(a[mf][3]),
                          "r"(b[nf][0]), "r"(b[nf][1]));
                }
        }
    }

    // Epilogue: raw fp32 accumulators straight to d_out (no scale).
    const size_t obase = (size_t)bm * BM * NDIM + (size_t)bn * BN;
    #pragma unroll
    for (int mf = 0; mf < 4; ++mf)
        #pragma unroll
        for (int nf = 0; nf < 4; ++nf) {
            int r0 = warp_m * 64 + mf * 16 + (lane >> 2);
            int c0 = warp_n * 32 + nf * 8 + 2 * (lane & 3);
            float* op = &out[obase + (size_t)r0 * NDIM + c0];
            op[0] = acc[mf][nf][0];
            op[1] = acc[mf][nf][1];
            float* op2 = op + 8 * NDIM;
            op2[0] = acc[mf][nf][2];
            op2[1] = acc[mf][nf][3];
        }
}

// ---------------- launch ----------------------
extern "C" void kernel_launch(void* const* d_in, const int* in_sizes, int n_in,
                              void* d_out, int out_size) {
    const float* x = (const float*)d_in[0];
    const float* w = (const float*)d_in[1];
    if (n_in >= 2 && in_sizes[0] == NDIM * KDIM && in_sizes[1] == MROWS * KDIM) {
        const float* t = x; x = w; w = t;
    }

    cudaFuncSetAttribute(k_gemm5, cudaFuncAttributeMaxDynamicSharedMemorySize, SMEM_DYN);

    k_cast_xw<<<2112, 256>>>(x, w);                                         // launch 1
    k_gemm5<<<dim3(NDIM / BN, MROWS / BM), 256, SMEM_DYN>>>((float*)d_out); // launch 2
}